// round 14
// baseline (speedup 1.0000x reference)
#include <cuda_runtime.h>
#include <cuda_bf16.h>

#define BB 32
#define SS 400
#define LL 50
#define EE 256
#define HH 512
#define AD 64
#define VV 50000
#define G3 (3*HH)
#define DKX (EE+HH+2*AD)

__device__ float g_x[SS*BB*EE];
__device__ float g_gi_f[SS*BB*G3];   // TRANSPOSED layout: [s][n][b]
__device__ float g_gi_b[SS*BB*G3];
__device__ float g_hs_f[SS*BB*HH];
__device__ float g_hs_b[SS*BB*HH];
__device__ float g_h[2][2][BB*HH];
__device__ float g_EH[(long)BB*SS*2*HH];
__device__ float g_PK[(long)BB*SS*HH];
__device__ float g_encfin[BB*2*HH];
__device__ float g_pe[LL*BB*EE];
__device__ float g_up[BB*2*AD];
__device__ float g_dech[2][BB*HH];
__device__ float g_chvec[BB*HH];
__device__ float g_qW[BB*HH];
__device__ float g_scores[BB*SS];
__device__ float g_alphas[BB*SS];
__device__ float g_qctxP[3*HH*BB];   // packed-transposed [k/4][b][4]
__device__ float g_logits[BB*VV];
__device__ float g_gp[BB];
__device__ unsigned g_vmaxkey[BB];
__device__ float g_vsumf[BB];
__device__ unsigned g_bar_count;
__device__ unsigned g_bar_gen;
__device__ unsigned g_dcnt;
__device__ unsigned g_dgen;

__device__ __forceinline__ float warp_sum(float v){
  #pragma unroll
  for (int o=16;o;o>>=1) v += __shfl_xor_sync(0xffffffffu,v,o);
  return v;
}
__device__ __forceinline__ float sigf(float x){ return __fdividef(1.f,1.f+__expf(-x)); }
__device__ __forceinline__ float tanh_acc(float x){
  float ax=fabsf(x), e=__expf(-2.f*ax);
  float r=__fdividef(1.f-e,1.f+e);
  return (x<0.f)?-r:r;
}
__device__ __forceinline__ float tanh_fast(float x){
  float y; asm("tanh.approx.f32 %0,%1;":"=f"(y):"f"(x)); return y;
}
// order-preserving float<->uint key for atomicMax over signed floats
__device__ __forceinline__ unsigned fkey(float f){
  unsigned u=__float_as_uint(f);
  return (f>=0.f)?(u|0x80000000u):(~u);
}
__device__ __forceinline__ float fdecode(unsigned k){
  return (k&0x80000000u)?__uint_as_float(k&0x7FFFFFFFu):__uint_as_float(~k);
}

// ---- fence-free sync primitives (no CCTL.IVALL) ----
__device__ __forceinline__ unsigned ld_acq(const unsigned* p){
  unsigned v;
  asm volatile("ld.acquire.gpu.global.u32 %0,[%1];":"=r"(v):"l"(p):"memory");
  return v;
}
__device__ __forceinline__ unsigned atom_add_acqrel(unsigned* p, unsigned v){
  unsigned o;
  asm volatile("atom.acq_rel.gpu.global.add.u32 %0,[%1],%2;":"=r"(o):"l"(p),"r"(v):"memory");
  return o;
}
__device__ __forceinline__ void red_add_rel(unsigned* p, unsigned v){
  asm volatile("red.release.gpu.global.add.u32 [%0],%1;"::"l"(p),"r"(v):"memory");
}

__global__ void k_embed(const int* __restrict__ src,const int* __restrict__ trg,
                        const int* __restrict__ user,const int* __restrict__ prod,
                        const float* __restrict__ embW,const float* __restrict__ userW,
                        const float* __restrict__ prodW){
  if (blockIdx.x==0 && threadIdx.x==0){
    g_bar_count=0u; g_bar_gen=0u; g_dcnt=0u; g_dgen=0u;
  }
  int t0=blockIdx.x*blockDim.x+threadIdx.x, st=gridDim.x*blockDim.x;
  for (int i=t0;i<BB;i+=st){ g_vmaxkey[i]=0u; g_vsumf[i]=0.f; }
  for (int i=t0;i<SS*BB*EE;i+=st){
    int e=i%EE, sb=i/EE, b=sb%BB, s=sb/BB;
    g_x[i]=embW[(long)src[b*SS+s]*EE+e];
  }
  for (int i=t0;i<LL*BB*EE;i+=st){
    int e=i%EE, tb=i/EE, b=tb%BB, t=tb/BB;
    int tok=(t==0)?1:trg[b*LL+t-1];
    g_pe[i]=embW[(long)tok*EE+e];
  }
  for (int i=t0;i<BB*2*AD;i+=st){
    int k=i%(2*AD), b=i/(2*AD);
    g_up[i]=(k<AD)?userW[(long)user[b]*AD+k]:prodW[(long)prod[b]*AD+(k-AD)];
  }
  for (int i=t0;i<2*BB*HH;i+=st){
    int d=i/(BB*HH);
    g_h[d][0][i-d*BB*HH]=0.f;
  }
}

// ---------------- fast fp32 GEMM (preamble) ----------------
template<bool TRG>
__global__ void __launch_bounds__(256) gemm_big(const float* __restrict__ A,
                                                const float* __restrict__ W,
                                                const float* __restrict__ bias,
                                                float* __restrict__ C,
                                                int M,int N,int K){
  constexpr int BM=64,BN=128,BK=32;
  __shared__ __align__(16) float As[BK][BM+4];
  __shared__ __align__(16) float Ws[BK][BN+4];
  int m0=blockIdx.y*BM, n0=blockIdx.x*BN, tid=threadIdx.x;
  int tn=tid&15, tm=tid>>4;
  float acc[4][8];
  #pragma unroll
  for (int i=0;i<4;i++)
    #pragma unroll
    for (int j=0;j<8;j++) acc[i][j]=0.f;
  for (int k0=0;k0<K;k0+=BK){
    #pragma unroll
    for (int i=tid;i<BM*BK/4;i+=256){
      int m=i>>3, kq=i&7;
      float4 v=*(const float4*)(A+(long)(m0+m)*K+k0+kq*4);
      As[kq*4+0][m]=v.x; As[kq*4+1][m]=v.y;
      As[kq*4+2][m]=v.z; As[kq*4+3][m]=v.w;
    }
    #pragma unroll
    for (int i=tid;i<BN*BK/4;i+=256){
      int n=i>>3, kq=i&7;
      float4 v=*(const float4*)(W+(long)(n0+n)*K+k0+kq*4);
      Ws[kq*4+0][n]=v.x; Ws[kq*4+1][n]=v.y;
      Ws[kq*4+2][n]=v.z; Ws[kq*4+3][n]=v.w;
    }
    __syncthreads();
    #pragma unroll
    for (int k=0;k<BK;k++){
      float a[4],w[8];
      *(float4*)a     = *(const float4*)&As[k][tm*4];
      *(float4*)w     = *(const float4*)&Ws[k][tn*8];
      *(float4*)(w+4) = *(const float4*)&Ws[k][tn*8+4];
      #pragma unroll
      for (int i=0;i<4;i++)
        #pragma unroll
        for (int j=0;j<8;j++) acc[i][j]+=a[i]*w[j];
    }
    __syncthreads();
  }
  #pragma unroll
  for (int i=0;i<4;i++){
    int m=m0+tm*4+i;
    #pragma unroll
    for (int j=0;j<8;j++){
      int n=n0+tn*8+j;
      float v=acc[i][j]+(bias?bias[n]:0.f);
      if (TRG) C[((long)(m>>5)*N+n)*32+(m&31)]=v;
      else     C[(long)m*N+n]=v;
    }
  }
}

// ---------------- persistent encoder (unchanged from round 10) ----------------
#define ENC_BLOCKS 128
#define W_SMEM (3*8*HH)
#define SMEM_ENC ((W_SMEM + BB*(HH+4))*4)
__global__ void __launch_bounds__(256,1) k_enc_persist(
                           const float* __restrict__ WhhF,const float* __restrict__ bhhF,
                           const float* __restrict__ WhhB,const float* __restrict__ bhhB){
  extern __shared__ float sm[];
  float* wsm=sm;
  float* hsm=sm+W_SMEM;
  int dir=blockIdx.x>>6, chunk=blockIdx.x&63;
  const float* Whh=dir?WhhB:WhhF;
  const float* bhh=dir?bhhB:bhhF;
  const float* gi =dir?g_gi_b:g_gi_f;
  float* hout =dir?g_hs_b:g_hs_f;
  int tid=threadIdx.x;
  int b=tid&31, jl=tid>>5;
  int j=chunk*8+jl;
  for (int q=tid;q<W_SMEM/4;q+=256){
    int g=q>>10, rem=q&1023, jl2=rem>>7, k4=rem&127;
    float4 v=*(const float4*)(Whh+((long)g*HH + chunk*8 + jl2)*HH + k4*4);
    *(float4*)(wsm+(g*8+jl2)*HH + k4*4)=v;
  }
  const float* wr=wsm+(0*8+jl)*HH;
  const float* wz=wsm+(1*8+jl)*HH;
  const float* wn=wsm+(2*8+jl)*HH;
  float br=bhh[j], bz=bhh[HH+j], bn=bhh[2*HH+j];
  unsigned gen_target=0;
  __syncthreads();

  for (int s=0;s<SS;s++){
    int par=s&1;
    const float* hprev=g_h[dir][par];
    float* hnext=g_h[dir][par^1];
    int sx=dir?(SS-1-s):s;
    for (int i=tid;i<BB*HH/4;i+=256){
      int bb=i>>7, k=(i&127)<<2;
      float4 v=__ldcg(((const float4*)hprev)+i);
      *(float4*)(hsm+bb*(HH+4)+k)=v;
    }
    long gio=(long)sx*(BB*G3);
    float ir=gi[gio+(0*HH+j)*32+b];
    float iz=gi[gio+(1*HH+j)*32+b];
    float in_=gi[gio+(2*HH+j)*32+b];
    __syncthreads();
    const float* hb=hsm+b*(HH+4);
    float ar=0,az=0,an=0;
    #pragma unroll 4
    for (int k=0;k<HH;k+=4){
      float4 h4=*(const float4*)(hb+k);
      float4 w;
      w=*(const float4*)(wr+k); ar+=w.x*h4.x+w.y*h4.y+w.z*h4.z+w.w*h4.w;
      w=*(const float4*)(wz+k); az+=w.x*h4.x+w.y*h4.y+w.z*h4.z+w.w*h4.w;
      w=*(const float4*)(wn+k); an+=w.x*h4.x+w.y*h4.y+w.z*h4.z+w.w*h4.w;
    }
    float r=sigf(ir+ar+br), z=sigf(iz+az+bz);
    float n=tanh_acc(in_+r*(an+bn));
    float hv=(1.f-z)*n+z*hb[j];
    __stcg(&hnext[b*HH+j],hv);
    hout[((long)sx*BB+b)*HH+j]=hv;
    __syncthreads();
    if (s<SS-1){
      if (tid==0){
        gen_target++;
        unsigned v=atom_add_acqrel(&g_bar_count,1u);
        if (v==ENC_BLOCKS-1){
          atomicExch(&g_bar_count,0u);
          red_add_rel(&g_bar_gen,1u);
        } else {
          while (ld_acq(&g_bar_gen) < gen_target) { }
        }
      }
      __syncthreads();
    }
  }
}

__global__ void k_postenc(){
  int t0=blockIdx.x*blockDim.x+threadIdx.x, st=gridDim.x*blockDim.x;
  for (int i=t0;i<BB*2*HH;i+=st){
    int b=i/(2*HH), k=i%(2*HH);
    g_encfin[i]=(k<HH)?g_hs_f[((long)399*BB+b)*HH+k]:g_hs_b[((long)0*BB+b)*HH+(k-HH)];
  }
  for (long i=t0;i<(long)BB*SS*2*HH;i+=st){
    int d=(int)(i%(2*HH));
    long bs=i/(2*HH);
    int s=(int)(bs%SS), b=(int)(bs/SS);
    g_EH[i]=(d<HH)?g_hs_f[((long)s*BB+b)*HH+d]:g_hs_b[((long)s*BB+b)*HH+(d-HH)];
  }
}

__global__ void k_hidden(const float* __restrict__ initW,const float* __restrict__ initB){
  int b=blockIdx.y;
  int n=blockIdx.x*8+(threadIdx.x>>5);
  int lane=threadIdx.x&31;
  const float* f=g_encfin+b*2*HH;
  const float* w=initW+n*2*HH;
  float acc=0;
  for (int k=lane;k<2*HH;k+=32) acc+=f[k]*w[k];
  acc=warp_sum(acc);
  if (lane==0){
    float hv=tanh_acc(acc+initB[n]);
    g_dech[0][b*HH+n]=hv;
    g_chvec[b*HH+n]=hv;
  }
}

// ================= PERSISTENT DECODER: all 50 steps, 1 launch =================
#define DEC_BLOCKS 128
#define DSM_F (BB*(HH+4) + BB*(DKX+4))      // 45312 floats = 181248 B
#define QUARTER (VV/4)                       // 12500
__global__ void __launch_bounds__(256,1) k_dec_persist(
    const float* __restrict__ dWih,const float* __restrict__ dWhh,
    const float* __restrict__ dbih,const float* __restrict__ dbhh,
    const float* __restrict__ queryW,const float* __restrict__ energW,
    const int*   __restrict__ mask,const float* __restrict__ chW,
    const float* __restrict__ genpW,const float* __restrict__ genpb,
    const float* __restrict__ genW,const int* __restrict__ src,
    float* __restrict__ out){
  extern __shared__ float dsm[];
  int tid=threadIdx.x, blk=blockIdx.x;
  int lane=tid&31;
  unsigned bt=0;

#define GBAR() do{ __syncthreads(); \
  if (tid==0){ bt++; \
    unsigned v=atom_add_acqrel(&g_dcnt,1u); \
    if (v==DEC_BLOCKS-1){ atomicExch(&g_dcnt,0u); red_add_rel(&g_dgen,1u); } \
    else { while (ld_acq(&g_dgen)<bt){} } } \
  __syncthreads(); }while(0)

  for (int t=0;t<LL;t++){
    int par=t&1, parn=par^1;
    // ---- P1: decoder GRU (blocks 0..63, j = blk*8 + (tid>>5)) ----
    if (blk<64){
      float* hs=dsm;
      float* xs=dsm+BB*(HH+4);
      const float* hprev=g_dech[par];
      float* hnext=g_dech[parn];
      for (int i=tid;i<BB*HH/4;i+=256){
        int bb=i>>7, k=(i&127)<<2;
        float4 v=__ldcg(((const float4*)hprev)+i);
        *(float4*)(hs+bb*(HH+4)+k)=v;
      }
      for (int i=tid;i<BB*DKX;i+=256){
        int b2=i/DKX, k=i%DKX; float v;
        if (k<EE) v=g_pe[(t*BB+b2)*EE+k];
        else if (k<EE+HH) v=__ldcg(&g_chvec[b2*HH+(k-EE)]);
        else v=g_up[b2*2*AD+(k-EE-HH)];
        xs[b2*(DKX+4)+k]=v;
      }
      __syncthreads();
      int b=tid&31, jl=tid>>5;
      int j=blk*8+jl;
      const float* hb=hs+b*(HH+4);
      const float* xb=xs+b*(DKX+4);
      float xr=0,xz=0,xn=0;
      {
        const float* w0=dWih+(long)j*DKX;
        const float* w1=dWih+(long)(HH+j)*DKX;
        const float* w2=dWih+(long)(2*HH+j)*DKX;
        #pragma unroll 4
        for (int k=0;k<DKX;k+=4){
          float4 x4=*(const float4*)(xb+k);
          float4 w;
          w=*(const float4*)(w0+k); xr+=w.x*x4.x+w.y*x4.y+w.z*x4.z+w.w*x4.w;
          w=*(const float4*)(w1+k); xz+=w.x*x4.x+w.y*x4.y+w.z*x4.z+w.w*x4.w;
          w=*(const float4*)(w2+k); xn+=w.x*x4.x+w.y*x4.y+w.z*x4.z+w.w*x4.w;
        }
      }
      float hr=0,hz=0,hn=0;
      {
        const float* w0=dWhh+(long)j*HH;
        const float* w1=dWhh+(long)(HH+j)*HH;
        const float* w2=dWhh+(long)(2*HH+j)*HH;
        #pragma unroll 4
        for (int k=0;k<HH;k+=4){
          float4 h4=*(const float4*)(hb+k);
          float4 w;
          w=*(const float4*)(w0+k); hr+=w.x*h4.x+w.y*h4.y+w.z*h4.z+w.w*h4.w;
          w=*(const float4*)(w1+k); hz+=w.x*h4.x+w.y*h4.y+w.z*h4.z+w.w*h4.w;
          w=*(const float4*)(w2+k); hn+=w.x*h4.x+w.y*h4.y+w.z*h4.z+w.w*h4.w;
        }
      }
      float ir=xr+dbih[j], iz=xz+dbih[HH+j], in_=xn+dbih[2*HH+j];
      float gr=hr+dbhh[j], gz=hz+dbhh[HH+j], gn=hn+dbhh[2*HH+j];
      float r=sigf(ir+gr), z=sigf(iz+gz);
      float n=tanh_acc(in_+r*gn);
      __stcg(&hnext[b*HH+j],(1.f-z)*n+z*hb[j]);
    }
    GBAR();
    // ---- P2: qW = h @ queryW^T (warp per (n,b), x16) ----
    {
      int w=blk*8+(tid>>5);
      for (int p=w;p<BB*HH;p+=DEC_BLOCKS*8){
        int b=p&31, n=p>>5;
        const float* hb=g_dech[parn]+b*HH;
        const float* wq=queryW+(long)n*HH;
        float acc=0;
        for (int k=lane;k<HH;k+=32) acc+=__ldcg(hb+k)*wq[k];
        acc=warp_sum(acc);
        if (lane==0) g_qW[b*HH+n]=acc;
      }
    }
    GBAR();
    // ---- P3: scores (warp per (b,s)) ----
    {
      int w=blk*8+(tid>>5);
      for (int p=w;p<BB*SS;p+=DEC_BLOCKS*8){
        int b=p/SS, s=p-b*SS;
        const float* pk=g_PK+((long)b*SS+s)*HH;
        const float* qv=g_qW+b*HH;
        float acc=0;
        for (int k=lane;k<HH;k+=32) acc+=energW[k]*tanh_fast(__ldcg(qv+k)+pk[k]);
        acc=warp_sum(acc);
        if (lane==0) g_scores[b*SS+s]=(mask[b*SS+s]==0)?-1e30f:acc;
      }
    }
    GBAR();
    // ---- P4: softmax + context + qctx pack + gp (blocks 0..31, b=blk) ----
    if (blk<32){
      float* sal=dsm;
      float* red=dsm+512;
      int b=blk;
      const float* sc=g_scores+b*SS;
      float m=-1e30f;
      for (int s=tid;s<SS;s+=256) m=fmaxf(m,__ldcg(sc+s));
      red[tid]=m; __syncthreads();
      for (int st2=128;st2;st2>>=1){ if(tid<st2) red[tid]=fmaxf(red[tid],red[tid+st2]); __syncthreads(); }
      m=red[0]; __syncthreads();
      float sum=0;
      for (int s=tid;s<SS;s+=256){ float e=__expf(__ldcg(sc+s)-m); sal[s]=e; sum+=e; }
      red[tid]=sum; __syncthreads();
      for (int st2=128;st2;st2>>=1){ if(tid<st2) red[tid]+=red[tid+st2]; __syncthreads(); }
      float inv=__fdividef(1.f,red[0]);
      __syncthreads();
      for (int s=tid;s<SS;s+=256){ float a=sal[s]*inv; sal[s]=a; g_alphas[b*SS+s]=a; }
      __syncthreads();
      float4 acc4=make_float4(0.f,0.f,0.f,0.f);
      const float* ehb=g_EH+(long)b*SS*(2*HH)+tid*4;
      #pragma unroll 4
      for (int s=0;s<SS;s++){
        float a=sal[s];
        float4 eh=*(const float4*)(ehb+(long)s*(2*HH));
        acc4.x+=a*eh.x; acc4.y+=a*eh.y; acc4.z+=a*eh.z; acc4.w+=a*eh.w;
      }
      *(float4*)(g_qctxP+(128+tid)*128+b*4)=acc4;    // ctx at k1 = 512 + tid*4
      float4 qv4=make_float4(0.f,0.f,0.f,0.f);
      if (tid<128){
        qv4=__ldcg(((const float4*)(g_dech[parn]+b*HH))+tid);
        *(float4*)(g_qctxP+tid*128+b*4)=qv4;
      }
      float gpp=acc4.x*genpW[tid*4]+acc4.y*genpW[tid*4+1]
               +acc4.z*genpW[tid*4+2]+acc4.w*genpW[tid*4+3];
      if (tid<128)
        gpp+=qv4.x*genpW[2*HH+tid*4]+qv4.y*genpW[2*HH+tid*4+1]
            +qv4.z*genpW[2*HH+tid*4+2]+qv4.w*genpW[2*HH+tid*4+3];
      if (tid<64){
        float4 p4=*((const float4*)(g_pe+(t*BB+b)*EE)+tid);
        gpp+=p4.x*genpW[3*HH+tid*4]+p4.y*genpW[3*HH+tid*4+1]
            +p4.z*genpW[3*HH+tid*4+2]+p4.w*genpW[3*HH+tid*4+3];
      }
      red[tid]=gpp; __syncthreads();
      for (int st2=128;st2;st2>>=1){ if(tid<st2) red[tid]+=red[tid+st2]; __syncthreads(); }
      if (tid==0) g_gp[b]=sigf(red[0]+genpb[0]);
    }
    GBAR();
    // ---- P5: ch = tanh([q,ctx] @ chW^T) (blocks 0..63) ----
    if (blk<64){
      float* wsm=dsm;                    // 8 x 1536
      int n0=blk*8;
      for (int i=tid;i<8*3*HH/4;i+=256){
        int r=i/384, kq=i%384;
        *(float4*)(wsm+r*3*HH+kq*4)=*(const float4*)(chW+(long)(n0+r)*3*HH+kq*4);
      }
      __syncthreads();
      int b=tid&31, wl=tid>>5;
      const float* w=wsm+wl*3*HH;
      float acc=0;
      #pragma unroll 4
      for (int kq=0;kq<3*HH/4;kq++){
        float4 x=__ldcg((const float4*)(g_qctxP+kq*128+b*4));
        float4 ww=*(const float4*)(w+kq*4);
        acc+=ww.x*x.x+ww.y*x.y+ww.z*x.z+ww.w*x.w;
      }
      g_chvec[b*HH+n0+wl]=tanh_acc(acc);
    }
    GBAR();
    // ---- P6: logits = chvec @ genW^T (BM=32,BN=256,BK=32) + register-local max ----
    {
      float* As=dsm;                     // 32 x 36
      float* Ws=dsm+32*36;               // 32 x 260
      int tn=tid&31, tm=tid>>5;
      float lmax[4]={-1e30f,-1e30f,-1e30f,-1e30f};
      for (int tile=blk; tile<196; tile+=DEC_BLOCKS){
        int n0=tile*256;
        float acc[4][8];
        #pragma unroll
        for (int i=0;i<4;i++)
          #pragma unroll
          for (int j=0;j<8;j++) acc[i][j]=0.f;
        for (int k0=0;k0<HH;k0+=32){
          {
            int mrow=tid>>3, kq=tid&7;
            float4 v=__ldcg(((const float4*)(g_chvec+(long)mrow*HH+k0))+kq);
            As[(kq*4+0)*36+mrow]=v.x; As[(kq*4+1)*36+mrow]=v.y;
            As[(kq*4+2)*36+mrow]=v.z; As[(kq*4+3)*36+mrow]=v.w;
          }
          #pragma unroll
          for (int i=tid;i<2048;i+=256){
            int n=i>>3, kq=i&7;
            int gn=n0+n;
            float4 v;
            if (gn<VV) v=*((const float4*)(genW+(long)gn*HH+k0)+kq);
            else { v.x=v.y=v.z=v.w=0.f; }
            Ws[(kq*4+0)*260+n]=v.x; Ws[(kq*4+1)*260+n]=v.y;
            Ws[(kq*4+2)*260+n]=v.z; Ws[(kq*4+3)*260+n]=v.w;
          }
          __syncthreads();
          #pragma unroll
          for (int k=0;k<32;k++){
            float a[4],w8[8];
            *(float4*)a      = *(const float4*)&As[k*36+tm*4];
            *(float4*)w8     = *(const float4*)&Ws[k*260+tn*8];
            *(float4*)(w8+4) = *(const float4*)&Ws[k*260+tn*8+4];
            #pragma unroll
            for (int i=0;i<4;i++)
              #pragma unroll
              for (int j=0;j<8;j++) acc[i][j]+=a[i]*w8[j];
          }
          __syncthreads();
        }
        #pragma unroll
        for (int i=0;i<4;i++){
          int mm=tm*4+i;
          float* lrow=g_logits+(long)mm*VV;
          #pragma unroll
          for (int j=0;j<8;j+=4){
            int n=n0+tn*8+j;
            if (n+3<VV){
              float4 v; v.x=acc[i][j]; v.y=acc[i][j+1]; v.z=acc[i][j+2]; v.w=acc[i][j+3];
              *(float4*)(lrow+n)=v;
            } else {
              for (int q=0;q<4;q++) if (n+q<VV) lrow[n+q]=acc[i][j+q];
            }
          }
          #pragma unroll
          for (int j=0;j<8;j++){
            int n=n0+tn*8+j;
            if (n<VV) lmax[i]=fmaxf(lmax[i],acc[i][j]);
          }
        }
      }
      // per-warp reduce (lanes share tm), lane0 atomicMax per m-row
      #pragma unroll
      for (int i=0;i<4;i++){
        float v=lmax[i];
        #pragma unroll
        for (int o=16;o;o>>=1) v=fmaxf(v,__shfl_xor_sync(0xffffffffu,v,o));
        if (lane==0) atomicMax(&g_vmaxkey[tm*4+i],fkey(v));
      }
    }
    GBAR();
    // ---- P7: exp in-place + per-b sum (4 blocks per b) ----
    {
      float* red=dsm;
      int b=blk>>2, q=blk&3;
      float m=fdecode(__ldcg(&g_vmaxkey[b]));
      float* lg=g_logits+(long)b*VV;
      int base=q*QUARTER;
      float sum=0;
      for (int v=base+tid*4; v<base+QUARTER; v+=1024){
        float4 x=__ldcg((const float4*)(lg+v));
        float4 e;
        e.x=__expf(x.x-m); e.y=__expf(x.y-m);
        e.z=__expf(x.z-m); e.w=__expf(x.w-m);
        *(float4*)(lg+v)=e;
        sum+=e.x+e.y+e.z+e.w;
      }
      red[tid]=sum; __syncthreads();
      for (int st2=128;st2;st2>>=1){ if(tid<st2) red[tid]+=red[tid+st2]; __syncthreads(); }
      if (tid==0) atomicAdd(&g_vsumf[b],red[0]);
    }
    GBAR();
    // ---- P8: dense output write ----
    {
      int b=blk>>2, q=blk&3;
      float gp=__ldcg(&g_gp[b]);
      float sv=__ldcg(&g_vsumf[b]);
      float inv=__fdividef(gp,sv);
      const float* lg=g_logits+(long)b*VV;
      float* ob=out+(long)b*LL*VV+(long)t*VV;
      int base=q*QUARTER;
      for (int v=base+tid*4; v<base+QUARTER; v+=1024){
        float4 e=*(const float4*)(lg+v);     // own block wrote this quarter in P7
        float4 y; y.x=e.x*inv; y.y=e.y*inv; y.z=e.z*inv; y.w=e.w*inv;
        *(float4*)(ob+v)=y;
      }
    }
    GBAR();
    // ---- P9: copy scatter + reset (blocks 0..31) ----
    if (blk<32){
      int b=blk;
      float gp=g_gp[b];                    // same block wrote it in P4
      float* ob=out+(long)b*LL*VV+(long)t*VV;
      for (int s=tid;s<SS;s+=256)
        atomicAdd(&ob[src[b*SS+s]], (1.f-gp)*g_alphas[b*SS+s]);
      if (tid==0){ g_vmaxkey[b]=0u; g_vsumf[b]=0.f; }
    }
    // no barrier needed: next-step phases that touch these buffers are behind >=1 barrier
  }
#undef GBAR
}

extern "C" void kernel_launch(void* const* d_in, const int* in_sizes, int n_in,
                              void* d_out, int out_size){
  int w=(in_sizes[5]==1)?6:5;
  const int* src =(const int*)d_in[0];
  const int* trg =(const int*)d_in[1];
  const int* user=(const int*)d_in[2];
  const int* prod=(const int*)d_in[3];
  const int* mask=(const int*)d_in[4];
  const float* embW  =(const float*)d_in[w+0];
  const float* userW =(const float*)d_in[w+1];
  const float* prodW =(const float*)d_in[w+2];
  const float* WihF  =(const float*)d_in[w+3];
  const float* WhhF  =(const float*)d_in[w+4];
  const float* bihF  =(const float*)d_in[w+5];
  const float* bhhF  =(const float*)d_in[w+6];
  const float* WihB  =(const float*)d_in[w+7];
  const float* WhhB  =(const float*)d_in[w+8];
  const float* bihB  =(const float*)d_in[w+9];
  const float* bhhB  =(const float*)d_in[w+10];
  const float* initW =(const float*)d_in[w+11];
  const float* initB =(const float*)d_in[w+12];
  const float* keyW  =(const float*)d_in[w+13];
  const float* queryW=(const float*)d_in[w+14];
  const float* energW=(const float*)d_in[w+15];
  const float* dWih  =(const float*)d_in[w+16];
  const float* dWhh  =(const float*)d_in[w+17];
  const float* dbih  =(const float*)d_in[w+18];
  const float* dbhh  =(const float*)d_in[w+19];
  const float* chW   =(const float*)d_in[w+20];
  const float* genpW =(const float*)d_in[w+21];
  const float* genpb =(const float*)d_in[w+22];
  const float* genW  =(const float*)d_in[w+23];
  float* out=(float*)d_out;

  float *pX,*pGiF,*pGiB,*pEH,*pPK;
  cudaGetSymbolAddress((void**)&pX,   g_x);
  cudaGetSymbolAddress((void**)&pGiF, g_gi_f);
  cudaGetSymbolAddress((void**)&pGiB, g_gi_b);
  cudaGetSymbolAddress((void**)&pEH,  g_EH);
  cudaGetSymbolAddress((void**)&pPK,  g_PK);

  cudaFuncSetAttribute(k_enc_persist, cudaFuncAttributeMaxDynamicSharedMemorySize, SMEM_ENC);
  cudaFuncSetAttribute(k_dec_persist, cudaFuncAttributeMaxDynamicSharedMemorySize, DSM_F*4);

  k_embed<<<1024,256>>>(src,trg,user,prod,embW,userW,prodW);

  {
    dim3 g(G3/128, (SS*BB)/64);
    gemm_big<true><<<g,256>>>(pX, WihF, bihF, pGiF, SS*BB, G3, EE);
    gemm_big<true><<<g,256>>>(pX, WihB, bihB, pGiB, SS*BB, G3, EE);
  }

  k_enc_persist<<<ENC_BLOCKS,256,SMEM_ENC>>>(WhhF,bhhF,WhhB,bhhB);

  k_postenc<<<2048,256>>>();

  {
    dim3 g(HH/128, (SS*BB)/64);
    gemm_big<false><<<g,256>>>(pEH, keyW, nullptr, pPK, SS*BB, HH, 2*HH);
  }

  k_hidden<<<dim3(HH/8,BB),256>>>(initW, initB);

  k_dec_persist<<<DEC_BLOCKS,256,DSM_F*4>>>(dWih,dWhh,dbih,dbhh,queryW,energW,
                                            mask,chW,genpW,genpb,genW,src,out);
}

// round 15
// speedup vs baseline: 1.1680x; 1.1680x over previous
#include <cuda_runtime.h>
#include <cuda_bf16.h>

#define BB 32
#define SS 400
#define LL 50
#define EE 256
#define HH 512
#define AD 64
#define VV 50000
#define G3 (3*HH)
#define DKX (EE+HH+2*AD)

__device__ float g_x[SS*BB*EE];
__device__ float g_gi_f[SS*BB*G3];   // TRANSPOSED layout: [s][n][b]
__device__ float g_gi_b[SS*BB*G3];
__device__ float g_hs_f[SS*BB*HH];
__device__ float g_hs_b[SS*BB*HH];
__device__ float g_h[2][2][BB*HH];
__device__ float g_EH[(long)BB*SS*2*HH];
__device__ float g_PK[(long)BB*SS*HH];
__device__ float g_encfin[BB*2*HH];
__device__ float g_pe[LL*BB*EE];
__device__ float g_up[BB*2*AD];
__device__ float g_dech[2][BB*HH];
__device__ float g_chvec[BB*HH];
__device__ float g_qW[BB*HH];
__device__ float g_scores[BB*SS];
__device__ float g_alphas[BB*SS];
__device__ float g_context[BB*2*HH];
__device__ float g_logits[BB*VV];
__device__ float g_gp[BB];
__device__ unsigned g_bar_count;
__device__ unsigned g_bar_gen;

__device__ __forceinline__ float warp_sum(float v){
  #pragma unroll
  for (int o=16;o;o>>=1) v += __shfl_xor_sync(0xffffffffu,v,o);
  return v;
}
__device__ __forceinline__ float sigf(float x){ return __fdividef(1.f,1.f+__expf(-x)); }
__device__ __forceinline__ float tanh_acc(float x){
  float ax=fabsf(x), e=__expf(-2.f*ax);
  float r=__fdividef(1.f-e,1.f+e);
  return (x<0.f)?-r:r;
}
__device__ __forceinline__ float to_tf32(float x){
  float y; asm("cvt.rna.tf32.f32 %0,%1;":"=f"(y):"f"(x)); return y;
}

// ---- fence-free sync primitives (no CCTL.IVALL) ----
__device__ __forceinline__ unsigned ld_acq(const unsigned* p){
  unsigned v;
  asm volatile("ld.acquire.gpu.global.u32 %0,[%1];":"=r"(v):"l"(p):"memory");
  return v;
}
__device__ __forceinline__ unsigned atom_add_acqrel(unsigned* p, unsigned v){
  unsigned o;
  asm volatile("atom.acq_rel.gpu.global.add.u32 %0,[%1],%2;":"=r"(o):"l"(p),"r"(v):"memory");
  return o;
}
__device__ __forceinline__ void red_add_rel(unsigned* p, unsigned v){
  asm volatile("red.release.gpu.global.add.u32 [%0],%1;"::"l"(p),"r"(v):"memory");
}

__global__ void k_embed(const int* __restrict__ src,const int* __restrict__ trg,
                        const int* __restrict__ user,const int* __restrict__ prod,
                        const float* __restrict__ embW,const float* __restrict__ userW,
                        const float* __restrict__ prodW){
  if (blockIdx.x==0 && threadIdx.x==0){ g_bar_count=0u; g_bar_gen=0u; }
  int t0=blockIdx.x*blockDim.x+threadIdx.x, st=gridDim.x*blockDim.x;
  for (int i=t0;i<SS*BB*EE;i+=st){
    int e=i%EE, sb=i/EE, b=sb%BB, s=sb/BB;
    g_x[i]=embW[(long)src[b*SS+s]*EE+e];
  }
  for (int i=t0;i<LL*BB*EE;i+=st){
    int e=i%EE, tb=i/EE, b=tb%BB, t=tb/BB;
    int tok=(t==0)?1:trg[b*LL+t-1];
    g_pe[i]=embW[(long)tok*EE+e];
  }
  for (int i=t0;i<BB*2*AD;i+=st){
    int k=i%(2*AD), b=i/(2*AD);
    g_up[i]=(k<AD)?userW[(long)user[b]*AD+k]:prodW[(long)prod[b]*AD+(k-AD)];
  }
  for (int i=t0;i<2*BB*HH;i+=st){
    int d=i/(BB*HH);
    g_h[d][0][i-d*BB*HH]=0.f;
  }
}

// C[m][n] = sum_k A[m][k]*W[n][k] (+bias[n]); TRG: write C as [m/32][n][m%32]
template<int BM,int BN,int BK,int TM,int TN,bool TRG>
__global__ void gemm_atb(const float* __restrict__ A,const float* __restrict__ W,
                         const float* __restrict__ bias,float* __restrict__ C,
                         int M,int N,int K){
  constexpr int THREADS=(BM/TM)*(BN/TN);
  __shared__ float As[BK][BM+1];
  __shared__ float Ws[BK][BN+1];
  int m0=blockIdx.y*BM, n0=blockIdx.x*BN, tid=threadIdx.x;
  int tn=tid%(BN/TN), tm=tid/(BN/TN);
  float acc[TM][TN];
  #pragma unroll
  for (int i=0;i<TM;i++)
    #pragma unroll
    for (int j=0;j<TN;j++) acc[i][j]=0.f;
  for (int k0=0;k0<K;k0+=BK){
    for (int i=tid;i<BM*BK;i+=THREADS){
      int r=i/BK,c=i%BK; int m=m0+r;
      As[c][r]=(m<M)?A[(long)m*K+k0+c]:0.f;
    }
    for (int i=tid;i<BN*BK;i+=THREADS){
      int r=i/BK,c=i%BK; int n=n0+r;
      Ws[c][r]=(n<N)?W[(long)n*K+k0+c]:0.f;
    }
    __syncthreads();
    #pragma unroll
    for (int k=0;k<BK;k++){
      float a[TM],w[TN];
      #pragma unroll
      for (int i=0;i<TM;i++) a[i]=As[k][tm*TM+i];
      #pragma unroll
      for (int j=0;j<TN;j++) w[j]=Ws[k][tn*TN+j];
      #pragma unroll
      for (int i=0;i<TM;i++)
        #pragma unroll
        for (int j=0;j<TN;j++) acc[i][j]+=a[i]*w[j];
    }
    __syncthreads();
  }
  #pragma unroll
  for (int i=0;i<TM;i++){
    int m=m0+tm*TM+i; if(m>=M) continue;
    #pragma unroll
    for (int j=0;j<TN;j++){
      int n=n0+tn*TN+j; if(n>=N) continue;
      float v=acc[i][j]+(bias?bias[n]:0.f);
      if (TRG) C[((long)(m>>5)*N+n)*32+(m&31)]=v;
      else     C[(long)m*N+n]=v;
    }
  }
}

// ---------------- persistent encoder: weights in SMEM, coalesced gi, spin barrier ----------------
#define ENC_BLOCKS 128
#define W_SMEM (3*8*HH)
#define SMEM_ENC ((W_SMEM + BB*(HH+4))*4)
__global__ void __launch_bounds__(256,1) k_enc_persist(
                           const float* __restrict__ WhhF,const float* __restrict__ bhhF,
                           const float* __restrict__ WhhB,const float* __restrict__ bhhB){
  extern __shared__ float sm[];
  float* wsm=sm;
  float* hsm=sm+W_SMEM;
  int dir=blockIdx.x>>6, chunk=blockIdx.x&63;
  const float* Whh=dir?WhhB:WhhF;
  const float* bhh=dir?bhhB:bhhF;
  const float* gi =dir?g_gi_b:g_gi_f;
  float* hout =dir?g_hs_b:g_hs_f;
  int tid=threadIdx.x;
  int b=tid&31, jl=tid>>5;
  int j=chunk*8+jl;
  for (int q=tid;q<W_SMEM/4;q+=256){
    int g=q>>10, rem=q&1023, jl2=rem>>7, k4=rem&127;
    float4 v=*(const float4*)(Whh+((long)g*HH + chunk*8 + jl2)*HH + k4*4);
    *(float4*)(wsm+(g*8+jl2)*HH + k4*4)=v;
  }
  const float* wr=wsm+(0*8+jl)*HH;
  const float* wz=wsm+(1*8+jl)*HH;
  const float* wn=wsm+(2*8+jl)*HH;
  float br=bhh[j], bz=bhh[HH+j], bn=bhh[2*HH+j];
  unsigned gen_target=0;
  __syncthreads();

  for (int s=0;s<SS;s++){
    int par=s&1;
    const float* hprev=g_h[dir][par];
    float* hnext=g_h[dir][par^1];
    int sx=dir?(SS-1-s):s;
    for (int i=tid;i<BB*HH/4;i+=256){
      int bb=i>>7, k=(i&127)<<2;
      float4 v=__ldcg(((const float4*)hprev)+i);
      *(float4*)(hsm+bb*(HH+4)+k)=v;
    }
    long gio=(long)sx*(BB*G3);
    float ir=gi[gio+(0*HH+j)*32+b];
    float iz=gi[gio+(1*HH+j)*32+b];
    float in_=gi[gio+(2*HH+j)*32+b];
    __syncthreads();
    const float* hb=hsm+b*(HH+4);
    float ar=0,az=0,an=0;
    #pragma unroll 4
    for (int k=0;k<HH;k+=4){
      float4 h4=*(const float4*)(hb+k);
      float4 w;
      w=*(const float4*)(wr+k); ar+=w.x*h4.x+w.y*h4.y+w.z*h4.z+w.w*h4.w;
      w=*(const float4*)(wz+k); az+=w.x*h4.x+w.y*h4.y+w.z*h4.z+w.w*h4.w;
      w=*(const float4*)(wn+k); an+=w.x*h4.x+w.y*h4.y+w.z*h4.z+w.w*h4.w;
    }
    float r=sigf(ir+ar+br), z=sigf(iz+az+bz);
    float n=tanh_acc(in_+r*(an+bn));
    float hv=(1.f-z)*n+z*hb[j];
    __stcg(&hnext[b*HH+j],hv);
    hout[((long)sx*BB+b)*HH+j]=hv;
    __syncthreads();
    if (s<SS-1){
      if (tid==0){
        gen_target++;
        unsigned v=atom_add_acqrel(&g_bar_count,1u);
        if (v==ENC_BLOCKS-1){
          atomicExch(&g_bar_count,0u);
          red_add_rel(&g_bar_gen,1u);
        } else {
          while (ld_acq(&g_bar_gen) < gen_target) { }
        }
      }
      __syncthreads();
    }
  }
}

__global__ void k_postenc(){
  int t0=blockIdx.x*blockDim.x+threadIdx.x, st=gridDim.x*blockDim.x;
  for (int i=t0;i<BB*2*HH;i+=st){
    int b=i/(2*HH), k=i%(2*HH);
    g_encfin[i]=(k<HH)?g_hs_f[((long)399*BB+b)*HH+k]:g_hs_b[((long)0*BB+b)*HH+(k-HH)];
  }
  for (long i=t0;i<(long)BB*SS*2*HH;i+=st){
    int d=(int)(i%(2*HH));
    long bs=i/(2*HH);
    int s=(int)(bs%SS), b=(int)(bs/SS);
    g_EH[i]=(d<HH)?g_hs_f[((long)s*BB+b)*HH+d]:g_hs_b[((long)s*BB+b)*HH+(d-HH)];
  }
}

__global__ void k_hidden(const float* __restrict__ initW,const float* __restrict__ initB){
  int b=blockIdx.y;
  int n=blockIdx.x*8+(threadIdx.x>>5);
  int lane=threadIdx.x&31;
  const float* f=g_encfin+b*2*HH;
  const float* w=initW+n*2*HH;
  float acc=0;
  for (int k=lane;k<2*HH;k+=32) acc+=f[k]*w[k];
  acc=warp_sum(acc);
  if (lane==0){
    float hv=tanh_acc(acc+initB[n]);
    g_dech[0][b*HH+n]=hv;
    g_chvec[b*HH+n]=hv;
  }
}

// ---------------- decoder GRU step ----------------
#define SMEM_DEC ((BB*(HH+4)+BB*(DKX+4))*4)
__global__ void __launch_bounds__(128,1) k_dec_step(int t,int par,
                           const float* __restrict__ Wih,const float* __restrict__ Whh,
                           const float* __restrict__ bih,const float* __restrict__ bhh){
  extern __shared__ float smd[];
  float* hs=smd;
  float* xs=smd+BB*(HH+4);
  int tid=threadIdx.x;
  const float* hprev=g_dech[par];
  float* hnext=g_dech[par^1];
  for (int i=tid;i<BB*HH/4;i+=128){
    int bb=i>>7, k=(i&127)<<2;
    *(float4*)(hs+bb*(HH+4)+k)=((const float4*)hprev)[i];
  }
  for (int i=tid;i<BB*DKX;i+=128){
    int b=i/DKX, k=i%DKX; float v;
    if (k<EE) v=g_pe[(t*BB+b)*EE+k];
    else if (k<EE+HH) v=g_chvec[b*HH+(k-EE)];
    else v=g_up[b*2*AD+(k-EE-HH)];
    xs[b*(DKX+4)+k]=v;
  }
  __syncthreads();
  int b=tid&31, jl=tid>>5;
  int j=blockIdx.x*4+jl;
  const float* hb=hs+b*(HH+4);
  const float* xb=xs+b*(DKX+4);
  float xr=0,xz=0,xn=0;
  {
    const float* w0=Wih+(long)j*DKX;
    const float* w1=Wih+(long)(HH+j)*DKX;
    const float* w2=Wih+(long)(2*HH+j)*DKX;
    #pragma unroll 4
    for (int k=0;k<DKX;k+=4){
      float4 x4=*(const float4*)(xb+k);
      float4 w;
      w=*(const float4*)(w0+k); xr+=w.x*x4.x+w.y*x4.y+w.z*x4.z+w.w*x4.w;
      w=*(const float4*)(w1+k); xz+=w.x*x4.x+w.y*x4.y+w.z*x4.z+w.w*x4.w;
      w=*(const float4*)(w2+k); xn+=w.x*x4.x+w.y*x4.y+w.z*x4.z+w.w*x4.w;
    }
  }
  float hr=0,hz=0,hn=0;
  {
    const float* w0=Whh+(long)j*HH;
    const float* w1=Whh+(long)(HH+j)*HH;
    const float* w2=Whh+(long)(2*HH+j)*HH;
    #pragma unroll 4
    for (int k=0;k<HH;k+=4){
      float4 h4=*(const float4*)(hb+k);
      float4 w;
      w=*(const float4*)(w0+k); hr+=w.x*h4.x+w.y*h4.y+w.z*h4.z+w.w*h4.w;
      w=*(const float4*)(w1+k); hz+=w.x*h4.x+w.y*h4.y+w.z*h4.z+w.w*h4.w;
      w=*(const float4*)(w2+k); hn+=w.x*h4.x+w.y*h4.y+w.z*h4.z+w.w*h4.w;
    }
  }
  float ir=xr+bih[j], iz=xz+bih[HH+j], in_=xn+bih[2*HH+j];
  float gr=hr+bhh[j], gz=hz+bhh[HH+j], gn=hn+bhh[2*HH+j];
  float r=sigf(ir+gr), z=sigf(iz+gz);
  float n=tanh_acc(in_+r*gn);
  hnext[b*HH+j]=(1.f-z)*n+z*hb[j];
}

__global__ void k_qw(const float* __restrict__ queryW,int parn){
  int b=blockIdx.y;
  int n=blockIdx.x*8+(threadIdx.x>>5);
  int lane=threadIdx.x&31;
  const float* h=g_dech[parn]+b*HH;
  const float* w=queryW+n*HH;
  float acc=0;
  for (int k=lane;k<HH;k+=32) acc+=h[k]*w[k];
  acc=warp_sum(acc);
  if (lane==0) g_qW[b*HH+n]=acc;
}

__global__ void k_scores(const float* __restrict__ energyW,const int* __restrict__ mask){
  __shared__ float sq[HH];
  __shared__ float se[HH];
  int b=blockIdx.y, tid=threadIdx.x;
  for (int k=tid;k<HH;k+=256){ sq[k]=g_qW[b*HH+k]; se[k]=energyW[k]; }
  __syncthreads();
  int s=blockIdx.x*8+(tid>>5);
  int lane=tid&31;
  if (s<SS){
    const float* pk=g_PK+((long)b*SS+s)*HH;
    float acc=0;
    for (int k=lane;k<HH;k+=32) acc+=se[k]*tanh_acc(sq[k]+pk[k]);
    acc=warp_sum(acc);
    if (lane==0) g_scores[b*SS+s]=(mask[b*SS+s]==0)?-1e30f:acc;
  }
}

// fused: softmax over scores -> alphas; context = alphas @ EH; gp
__global__ void __launch_bounds__(1024) k_attn(const float* __restrict__ genpW,
                                               const float* __restrict__ genpb,
                                               int parn,int t){
  int b=blockIdx.x, tid=threadIdx.x;
  __shared__ float sal[SS];
  __shared__ float red[1024];
  const float* sc=g_scores+b*SS;
  float m=-1e30f;
  if (tid<SS) m=sc[tid];
  red[tid]=m; __syncthreads();
  for (int st=512;st;st>>=1){ if(tid<st) red[tid]=fmaxf(red[tid],red[tid+st]); __syncthreads(); }
  m=red[0]; __syncthreads();
  float e=(tid<SS)?__expf(sc[tid]-m):0.f;
  red[tid]=e; __syncthreads();
  for (int st=512;st;st>>=1){ if(tid<st) red[tid]+=red[tid+st]; __syncthreads(); }
  float inv=__fdividef(1.f,red[0]);
  __syncthreads();
  if (tid<SS){ float a=e*inv; sal[tid]=a; g_alphas[b*SS+tid]=a; }
  __syncthreads();
  const float* eh=g_EH+(long)b*SS*2*HH+tid;
  float acc=0;
  #pragma unroll 8
  for (int s=0;s<SS;s++) acc+=sal[s]*eh[(long)s*(2*HH)];
  g_context[b*2*HH+tid]=acc;
  float gpp=acc*genpW[tid];
  if (tid<HH) gpp+=g_dech[parn][b*HH+tid]*genpW[2*HH+tid];
  if (tid<EE) gpp+=g_pe[(t*BB+b)*EE+tid]*genpW[3*HH+tid];
  red[tid]=gpp; __syncthreads();
  for (int st=512;st;st>>=1){ if(tid<st) red[tid]+=red[tid+st]; __syncthreads(); }
  if (tid==0) g_gp[b]=sigf(red[0]+genpb[0]);
}

__global__ void k_ch(const float* __restrict__ chW,int parn){
  int b=blockIdx.y;
  int n=blockIdx.x*8+(threadIdx.x>>5);
  int lane=threadIdx.x&31;
  const float* q=g_dech[parn]+b*HH;
  const float* c=g_context+b*2*HH;
  const float* w=chW+(long)n*3*HH;
  float acc=0;
  for (int k=lane;k<HH;k+=32) acc+=q[k]*w[k];
  for (int k=lane;k<2*HH;k+=32) acc+=c[k]*w[HH+k];
  acc=warp_sum(acc);
  if (lane==0) g_chvec[b*HH+n]=tanh_acc(acc);
}

// ---------------- logits = chvec @ genW^T on TENSOR CORES (tf32 mma.sync) ----------------
// block tile 32m x 128n, 8 warps (each 32m x 16n), k staged in 64-chunks.
#define GLS_SMEM ((32*520 + 128*68)*4)
__global__ void __launch_bounds__(256) k_genlogits_tf32(const float* __restrict__ A,
                                                        const float* __restrict__ W,
                                                        float* __restrict__ C){
  extern __shared__ float gls[];
  float* chS=gls;              // [32][520]
  float* BS =gls+32*520;       // [128][68]
  int tid=threadIdx.x, n0=blockIdx.x*128;
  int wid=tid>>5, lane=tid&31;
  // stage A (ch) rounded to tf32
  for (int i=tid;i<32*128;i+=256){
    int m=i>>7, kq=i&127;
    float4 v=*((const float4*)(A+(long)m*HH)+kq);
    float* p=chS+m*520+kq*4;
    p[0]=to_tf32(v.x); p[1]=to_tf32(v.y); p[2]=to_tf32(v.z); p[3]=to_tf32(v.w);
  }
  float d[2][2][4];
  #pragma unroll
  for (int mt=0;mt<2;mt++)
    #pragma unroll
    for (int nt=0;nt<2;nt++)
      #pragma unroll
      for (int q=0;q<4;q++) d[mt][nt][q]=0.f;

  int r=lane>>2, c=lane&3;
  for (int k0=0;k0<HH;k0+=64){
    // stage B chunk (genW[n][k0..k0+63]) rounded to tf32
    for (int i=tid;i<128*16;i+=256){
      int n=i>>4, kq=i&15;
      int gn=n0+n;
      float4 v;
      if (gn<VV) v=*((const float4*)(W+(long)gn*HH+k0)+kq);
      else { v.x=v.y=v.z=v.w=0.f; }
      float* p=BS+n*68+kq*4;
      p[0]=to_tf32(v.x); p[1]=to_tf32(v.y); p[2]=to_tf32(v.z); p[3]=to_tf32(v.w);
    }
    __syncthreads();
    #pragma unroll
    for (int kk=0;kk<64;kk+=8){
      unsigned a[2][4];
      #pragma unroll
      for (int mt=0;mt<2;mt++){
        const float* ap=chS+(mt*16+r)*520 + k0+kk+c;
        a[mt][0]=__float_as_uint(ap[0]);
        a[mt][1]=__float_as_uint(ap[8*520]);
        a[mt][2]=__float_as_uint(ap[4]);
        a[mt][3]=__float_as_uint(ap[8*520+4]);
      }
      unsigned bfr[2][2];
      #pragma unroll
      for (int nt=0;nt<2;nt++){
        const float* bp=BS+(wid*16+nt*8+r)*68 + kk+c;
        bfr[nt][0]=__float_as_uint(bp[0]);
        bfr[nt][1]=__float_as_uint(bp[4]);
      }
      #pragma unroll
      for (int mt=0;mt<2;mt++)
        #pragma unroll
        for (int nt=0;nt<2;nt++)
          asm volatile("mma.sync.aligned.m16n8k8.row.col.f32.tf32.tf32.f32 "
            "{%0,%1,%2,%3},{%4,%5,%6,%7},{%8,%9},{%0,%1,%2,%3};"
            :"+f"(d[mt][nt][0]),"+f"(d[mt][nt][1]),"+f"(d[mt][nt][2]),"+f"(d[mt][nt][3])
            :"r"(a[mt][0]),"r"(a[mt][1]),"r"(a[mt][2]),"r"(a[mt][3]),
             "r"(bfr[nt][0]),"r"(bfr[nt][1]));
    }
    __syncthreads();
  }
  // epilogue: d[mt][nt]: c0:(r, 2c) c1:(r, 2c+1) c2:(r+8, 2c) c3:(r+8, 2c+1)
  #pragma unroll
  for (int mt=0;mt<2;mt++)
    #pragma unroll
    for (int nt=0;nt<2;nt++){
      int m=mt*16+r;
      int n=n0+wid*16+nt*8+2*c;
      if (n<VV){    // VV even, n even -> n+1 also valid
        float2 v0; v0.x=d[mt][nt][0]; v0.y=d[mt][nt][1];
        float2 v1; v1.x=d[mt][nt][2]; v1.y=d[mt][nt][3];
        *(float2*)(C+(long)m*VV+n)=v0;
        *(float2*)(C+(long)(m+8)*VV+n)=v1;
      }
    }
}

__global__ void __launch_bounds__(1024) k_vocab_out(float* __restrict__ out,int t){
  int b=blockIdx.x, tid=threadIdx.x;
  __shared__ float red[1024];
  const float* lg=g_logits+(long)b*VV;
  float m=-1e30f;
  for (int v=tid*4;v<VV;v+=4096){
    float4 x=*(const float4*)(lg+v);
    m=fmaxf(m,fmaxf(fmaxf(x.x,x.y),fmaxf(x.z,x.w)));
  }
  red[tid]=m; __syncthreads();
  for (int st=512;st;st>>=1){ if(tid<st) red[tid]=fmaxf(red[tid],red[tid+st]); __syncthreads(); }
  m=red[0]; __syncthreads();
  float sum=0;
  for (int v=tid*4;v<VV;v+=4096){
    float4 x=*(const float4*)(lg+v);
    sum+=__expf(x.x-m)+__expf(x.y-m)+__expf(x.z-m)+__expf(x.w-m);
  }
  red[tid]=sum; __syncthreads();
  for (int st=512;st;st>>=1){ if(tid<st) red[tid]+=red[tid+st]; __syncthreads(); }
  float gp=g_gp[b];
  float inv=__fdividef(gp,red[0]);
  float* ob=out+(long)b*LL*VV+(long)t*VV;
  for (int v=tid*4;v<VV;v+=4096){
    float4 x=*(const float4*)(lg+v);
    float4 y;
    y.x=__expf(x.x-m)*inv; y.y=__expf(x.y-m)*inv;
    y.z=__expf(x.z-m)*inv; y.w=__expf(x.w-m)*inv;
    *(float4*)(ob+v)=y;
  }
}

__global__ void k_scatter(float* __restrict__ out,const int* __restrict__ src,int t){
  int i=blockIdx.x*256+threadIdx.x;
  if (i>=BB*SS) return;
  int b=i/SS, s=i%SS;
  float val=(1.f-g_gp[b])*g_alphas[i];
  atomicAdd(&out[(long)b*LL*VV+(long)t*VV+src[i]],val);
}

extern "C" void kernel_launch(void* const* d_in, const int* in_sizes, int n_in,
                              void* d_out, int out_size){
  int w=(in_sizes[5]==1)?6:5;
  const int* src =(const int*)d_in[0];
  const int* trg =(const int*)d_in[1];
  const int* user=(const int*)d_in[2];
  const int* prod=(const int*)d_in[3];
  const int* mask=(const int*)d_in[4];
  const float* embW  =(const float*)d_in[w+0];
  const float* userW =(const float*)d_in[w+1];
  const float* prodW =(const float*)d_in[w+2];
  const float* WihF  =(const float*)d_in[w+3];
  const float* WhhF  =(const float*)d_in[w+4];
  const float* bihF  =(const float*)d_in[w+5];
  const float* bhhF  =(const float*)d_in[w+6];
  const float* WihB  =(const float*)d_in[w+7];
  const float* WhhB  =(const float*)d_in[w+8];
  const float* bihB  =(const float*)d_in[w+9];
  const float* bhhB  =(const float*)d_in[w+10];
  const float* initW =(const float*)d_in[w+11];
  const float* initB =(const float*)d_in[w+12];
  const float* keyW  =(const float*)d_in[w+13];
  const float* queryW=(const float*)d_in[w+14];
  const float* energW=(const float*)d_in[w+15];
  const float* dWih  =(const float*)d_in[w+16];
  const float* dWhh  =(const float*)d_in[w+17];
  const float* dbih  =(const float*)d_in[w+18];
  const float* dbhh  =(const float*)d_in[w+19];
  const float* chW   =(const float*)d_in[w+20];
  const float* genpW =(const float*)d_in[w+21];
  const float* genpb =(const float*)d_in[w+22];
  const float* genW  =(const float*)d_in[w+23];
  float* out=(float*)d_out;

  float *pX,*pGiF,*pGiB,*pEH,*pPK,*pCh,*pLog;
  cudaGetSymbolAddress((void**)&pX,   g_x);
  cudaGetSymbolAddress((void**)&pGiF, g_gi_f);
  cudaGetSymbolAddress((void**)&pGiB, g_gi_b);
  cudaGetSymbolAddress((void**)&pEH,  g_EH);
  cudaGetSymbolAddress((void**)&pPK,  g_PK);
  cudaGetSymbolAddress((void**)&pCh,  g_chvec);
  cudaGetSymbolAddress((void**)&pLog, g_logits);

  cudaFuncSetAttribute(k_enc_persist,    cudaFuncAttributeMaxDynamicSharedMemorySize, SMEM_ENC);
  cudaFuncSetAttribute(k_dec_step,       cudaFuncAttributeMaxDynamicSharedMemorySize, SMEM_DEC);
  cudaFuncSetAttribute(k_genlogits_tf32, cudaFuncAttributeMaxDynamicSharedMemorySize, GLS_SMEM);

  k_embed<<<1024,256>>>(src,trg,user,prod,embW,userW,prodW);

  {
    dim3 g(G3/64, (SS*BB)/64);
    gemm_atb<64,64,32,4,4,true><<<g,256>>>(pX, WihF, bihF, pGiF, SS*BB, G3, EE);
    gemm_atb<64,64,32,4,4,true><<<g,256>>>(pX, WihB, bihB, pGiB, SS*BB, G3, EE);
  }

  k_enc_persist<<<ENC_BLOCKS,256,SMEM_ENC>>>(WhhF,bhhF,WhhB,bhhB);

  k_postenc<<<2048,256>>>();

  {
    dim3 g(HH/64, (SS*BB)/64);
    gemm_atb<64,64,32,4,4,false><<<g,256>>>(pEH, keyW, nullptr, pPK, SS*BB, HH, 2*HH);
  }

  k_hidden<<<dim3(HH/8,BB),256>>>(initW, initB);

  for (int t=0;t<LL;t++){
    int par=t&1;
    k_dec_step<<<128,128,SMEM_DEC>>>(t,par,dWih,dWhh,dbih,dbhh);
    k_qw<<<dim3(HH/8,BB),256>>>(queryW, par^1);
    k_scores<<<dim3(SS/8,BB),256>>>(energW, mask);
    k_attn<<<BB,1024>>>(genpW, genpb, par^1, t);
    k_ch<<<dim3(HH/8,BB),256>>>(chW, par^1);
    k_genlogits_tf32<<<(VV+127)/128,256,GLS_SMEM>>>(pCh, genW, pLog);
    k_vocab_out<<<BB,1024>>>(out, t);
    k_scatter<<<(BB*SS+255)/256,256>>>(out, src, t);
  }
}

// round 16
// speedup vs baseline: 1.2259x; 1.0495x over previous
#include <cuda_runtime.h>
#include <cuda_bf16.h>

#define BB 32
#define SS 400
#define LL 50
#define EE 256
#define HH 512
#define AD 64
#define VV 50000
#define G3 (3*HH)
#define DKX (EE+HH+2*AD)

__device__ float g_x[SS*BB*EE];
__device__ float g_gi_f[SS*BB*G3];   // TRANSPOSED layout: [s][n][b]
__device__ float g_gi_b[SS*BB*G3];
__device__ float g_hs_f[SS*BB*HH];
__device__ float g_hs_b[SS*BB*HH];
__device__ float g_h[2][2][BB*HH];
__device__ float g_EH[(long)BB*SS*2*HH];
__device__ float g_PK[(long)BB*SS*HH];
__device__ float g_encfin[BB*2*HH];
__device__ float g_pe[LL*BB*EE];
__device__ float g_up[BB*2*AD];
__device__ float g_dech[2][BB*HH];
__device__ float g_chvec[BB*HH];
__device__ float g_qW[BB*HH];
__device__ float g_scores[BB*SS];
__device__ float g_alphas[BB*SS];
__device__ float g_context[BB*2*HH];
__device__ float g_logits[BB*VV];
__device__ float g_gp[BB];
__device__ unsigned g_bar_count;
__device__ unsigned g_bar_gen;

__device__ __forceinline__ float warp_sum(float v){
  #pragma unroll
  for (int o=16;o;o>>=1) v += __shfl_xor_sync(0xffffffffu,v,o);
  return v;
}
__device__ __forceinline__ float sigf(float x){ return __fdividef(1.f,1.f+__expf(-x)); }
__device__ __forceinline__ float tanh_acc(float x){
  float ax=fabsf(x), e=__expf(-2.f*ax);
  float r=__fdividef(1.f-e,1.f+e);
  return (x<0.f)?-r:r;
}
__device__ __forceinline__ float to_tf32(float x){
  float y; asm("cvt.rna.tf32.f32 %0,%1;":"=f"(y):"f"(x)); return y;
}

// ---- fence-free sync primitives (no CCTL.IVALL) ----
__device__ __forceinline__ unsigned ld_acq(const unsigned* p){
  unsigned v;
  asm volatile("ld.acquire.gpu.global.u32 %0,[%1];":"=r"(v):"l"(p):"memory");
  return v;
}
__device__ __forceinline__ unsigned atom_add_acqrel(unsigned* p, unsigned v){
  unsigned o;
  asm volatile("atom.acq_rel.gpu.global.add.u32 %0,[%1],%2;":"=r"(o):"l"(p),"r"(v):"memory");
  return o;
}
__device__ __forceinline__ void red_add_rel(unsigned* p, unsigned v){
  asm volatile("red.release.gpu.global.add.u32 [%0],%1;"::"l"(p),"r"(v):"memory");
}

__global__ void k_embed(const int* __restrict__ src,const int* __restrict__ trg,
                        const int* __restrict__ user,const int* __restrict__ prod,
                        const float* __restrict__ embW,const float* __restrict__ userW,
                        const float* __restrict__ prodW){
  if (blockIdx.x==0 && threadIdx.x==0){ g_bar_count=0u; g_bar_gen=0u; }
  int t0=blockIdx.x*blockDim.x+threadIdx.x, st=gridDim.x*blockDim.x;
  for (int i=t0;i<SS*BB*EE;i+=st){
    int e=i%EE, sb=i/EE, b=sb%BB, s=sb/BB;
    g_x[i]=embW[(long)src[b*SS+s]*EE+e];
  }
  for (int i=t0;i<LL*BB*EE;i+=st){
    int e=i%EE, tb=i/EE, b=tb%BB, t=tb/BB;
    int tok=(t==0)?1:trg[b*LL+t-1];
    g_pe[i]=embW[(long)tok*EE+e];
  }
  for (int i=t0;i<BB*2*AD;i+=st){
    int k=i%(2*AD), b=i/(2*AD);
    g_up[i]=(k<AD)?userW[(long)user[b]*AD+k]:prodW[(long)prod[b]*AD+(k-AD)];
  }
  for (int i=t0;i<2*BB*HH;i+=st){
    int d=i/(BB*HH);
    g_h[d][0][i-d*BB*HH]=0.f;
  }
}

// ---------------- tf32 tensor-core GEMM: C[m][n]=sum_k A[m][k]*W[n][k] (+bias) ----------------
// block tile 64m x 128n, 8 warps (2x4), warp tile 32x32 (2x4 of m16n8k8), k-chunk 32.
// Requires M%64==0, N%128==0, K%32==0 (true for all preamble shapes).
template<bool TRG>
__global__ void __launch_bounds__(256) gemm_tf32(const float* __restrict__ A,
                                                 const float* __restrict__ W,
                                                 const float* __restrict__ bias,
                                                 float* __restrict__ C,
                                                 int M,int N,int K){
  __shared__ __align__(16) float AS[64*36];
  __shared__ __align__(16) float BS[128*36];
  int m0=blockIdx.y*64, n0=blockIdx.x*128, tid=threadIdx.x;
  int wid=tid>>5, lane=tid&31;
  int wm=wid&1, wn=wid>>1;           // 2 warps on m, 4 on n
  int r=lane>>2, c=lane&3;
  float d[2][4][4];
  #pragma unroll
  for (int mt=0;mt<2;mt++)
    #pragma unroll
    for (int nt=0;nt<4;nt++)
      #pragma unroll
      for (int q=0;q<4;q++) d[mt][nt][q]=0.f;

  for (int k0=0;k0<K;k0+=32){
    #pragma unroll
    for (int i=tid;i<512;i+=256){            // A: 64 rows x 8 float4
      int m=i>>3, kq=i&7;
      float4 v=*((const float4*)(A+(long)(m0+m)*K+k0)+kq);
      float* p=AS+m*36+kq*4;
      p[0]=to_tf32(v.x); p[1]=to_tf32(v.y); p[2]=to_tf32(v.z); p[3]=to_tf32(v.w);
    }
    #pragma unroll
    for (int i=tid;i<1024;i+=256){           // B: 128 rows x 8 float4
      int n=i>>3, kq=i&7;
      float4 v=*((const float4*)(W+(long)(n0+n)*K+k0)+kq);
      float* p=BS+n*36+kq*4;
      p[0]=to_tf32(v.x); p[1]=to_tf32(v.y); p[2]=to_tf32(v.z); p[3]=to_tf32(v.w);
    }
    __syncthreads();
    #pragma unroll
    for (int kk=0;kk<32;kk+=8){
      unsigned a[2][4];
      #pragma unroll
      for (int mt=0;mt<2;mt++){
        const float* ap=AS+(wm*32+mt*16+r)*36+kk+c;
        a[mt][0]=__float_as_uint(ap[0]);
        a[mt][1]=__float_as_uint(ap[8*36]);
        a[mt][2]=__float_as_uint(ap[4]);
        a[mt][3]=__float_as_uint(ap[8*36+4]);
      }
      unsigned bf[4][2];
      #pragma unroll
      for (int nt=0;nt<4;nt++){
        const float* bp=BS+(wn*32+nt*8+r)*36+kk+c;
        bf[nt][0]=__float_as_uint(bp[0]);
        bf[nt][1]=__float_as_uint(bp[4]);
      }
      #pragma unroll
      for (int mt=0;mt<2;mt++)
        #pragma unroll
        for (int nt=0;nt<4;nt++)
          asm volatile("mma.sync.aligned.m16n8k8.row.col.f32.tf32.tf32.f32 "
            "{%0,%1,%2,%3},{%4,%5,%6,%7},{%8,%9},{%0,%1,%2,%3};"
            :"+f"(d[mt][nt][0]),"+f"(d[mt][nt][1]),"+f"(d[mt][nt][2]),"+f"(d[mt][nt][3])
            :"r"(a[mt][0]),"r"(a[mt][1]),"r"(a[mt][2]),"r"(a[mt][3]),
             "r"(bf[nt][0]),"r"(bf[nt][1]));
    }
    __syncthreads();
  }
  // epilogue: c0:(m,n) c1:(m,n+1) c2:(m+8,n) c3:(m+8,n+1)
  #pragma unroll
  for (int mt=0;mt<2;mt++)
    #pragma unroll
    for (int nt=0;nt<4;nt++){
      int m=m0+wm*32+mt*16+r;
      int n=n0+wn*32+nt*8+2*c;
      float b0=bias?bias[n]:0.f, b1=bias?bias[n+1]:0.f;
      float v00=d[mt][nt][0]+b0, v01=d[mt][nt][1]+b1;
      float v10=d[mt][nt][2]+b0, v11=d[mt][nt][3]+b1;
      if (TRG){
        C[((long)(m>>5)*N+n  )*32+(m&31)]=v00;
        C[((long)(m>>5)*N+n+1)*32+(m&31)]=v01;
        int m8=m+8;
        C[((long)(m8>>5)*N+n  )*32+(m8&31)]=v10;
        C[((long)(m8>>5)*N+n+1)*32+(m8&31)]=v11;
      } else {
        float2 a0; a0.x=v00; a0.y=v01;
        float2 a1; a1.x=v10; a1.y=v11;
        *(float2*)(C+(long)m*N+n)=a0;
        *(float2*)(C+(long)(m+8)*N+n)=a1;
      }
    }
}

// ---------------- persistent encoder: weights in SMEM, coalesced gi, spin barrier ----------------
#define ENC_BLOCKS 128
#define W_SMEM (3*8*HH)
#define SMEM_ENC ((W_SMEM + BB*(HH+4))*4)
__global__ void __launch_bounds__(256,1) k_enc_persist(
                           const float* __restrict__ WhhF,const float* __restrict__ bhhF,
                           const float* __restrict__ WhhB,const float* __restrict__ bhhB){
  extern __shared__ float sm[];
  float* wsm=sm;
  float* hsm=sm+W_SMEM;
  int dir=blockIdx.x>>6, chunk=blockIdx.x&63;
  const float* Whh=dir?WhhB:WhhF;
  const float* bhh=dir?bhhB:bhhF;
  const float* gi =dir?g_gi_b:g_gi_f;
  float* hout =dir?g_hs_b:g_hs_f;
  int tid=threadIdx.x;
  int b=tid&31, jl=tid>>5;
  int j=chunk*8+jl;
  for (int q=tid;q<W_SMEM/4;q+=256){
    int g=q>>10, rem=q&1023, jl2=rem>>7, k4=rem&127;
    float4 v=*(const float4*)(Whh+((long)g*HH + chunk*8 + jl2)*HH + k4*4);
    *(float4*)(wsm+(g*8+jl2)*HH + k4*4)=v;
  }
  const float* wr=wsm+(0*8+jl)*HH;
  const float* wz=wsm+(1*8+jl)*HH;
  const float* wn=wsm+(2*8+jl)*HH;
  float br=bhh[j], bz=bhh[HH+j], bn=bhh[2*HH+j];
  unsigned gen_target=0;
  __syncthreads();

  for (int s=0;s<SS;s++){
    int par=s&1;
    const float* hprev=g_h[dir][par];
    float* hnext=g_h[dir][par^1];
    int sx=dir?(SS-1-s):s;
    for (int i=tid;i<BB*HH/4;i+=256){
      int bb=i>>7, k=(i&127)<<2;
      float4 v=__ldcg(((const float4*)hprev)+i);
      *(float4*)(hsm+bb*(HH+4)+k)=v;
    }
    long gio=(long)sx*(BB*G3);
    float ir=gi[gio+(0*HH+j)*32+b];
    float iz=gi[gio+(1*HH+j)*32+b];
    float in_=gi[gio+(2*HH+j)*32+b];
    __syncthreads();
    const float* hb=hsm+b*(HH+4);
    float ar=0,az=0,an=0;
    #pragma unroll 4
    for (int k=0;k<HH;k+=4){
      float4 h4=*(const float4*)(hb+k);
      float4 w;
      w=*(const float4*)(wr+k); ar+=w.x*h4.x+w.y*h4.y+w.z*h4.z+w.w*h4.w;
      w=*(const float4*)(wz+k); az+=w.x*h4.x+w.y*h4.y+w.z*h4.z+w.w*h4.w;
      w=*(const float4*)(wn+k); an+=w.x*h4.x+w.y*h4.y+w.z*h4.z+w.w*h4.w;
    }
    float r=sigf(ir+ar+br), z=sigf(iz+az+bz);
    float n=tanh_acc(in_+r*(an+bn));
    float hv=(1.f-z)*n+z*hb[j];
    __stcg(&hnext[b*HH+j],hv);
    hout[((long)sx*BB+b)*HH+j]=hv;
    __syncthreads();
    if (s<SS-1){
      if (tid==0){
        gen_target++;
        unsigned v=atom_add_acqrel(&g_bar_count,1u);
        if (v==ENC_BLOCKS-1){
          atomicExch(&g_bar_count,0u);
          red_add_rel(&g_bar_gen,1u);
        } else {
          while (ld_acq(&g_bar_gen) < gen_target) { }
        }
      }
      __syncthreads();
    }
  }
}

__global__ void k_postenc(){
  int t0=blockIdx.x*blockDim.x+threadIdx.x, st=gridDim.x*blockDim.x;
  for (int i=t0;i<BB*2*HH;i+=st){
    int b=i/(2*HH), k=i%(2*HH);
    g_encfin[i]=(k<HH)?g_hs_f[((long)399*BB+b)*HH+k]:g_hs_b[((long)0*BB+b)*HH+(k-HH)];
  }
  for (long i=t0;i<(long)BB*SS*2*HH;i+=st){
    int d=(int)(i%(2*HH));
    long bs=i/(2*HH);
    int s=(int)(bs%SS), b=(int)(bs/SS);
    g_EH[i]=(d<HH)?g_hs_f[((long)s*BB+b)*HH+d]:g_hs_b[((long)s*BB+b)*HH+(d-HH)];
  }
}

__global__ void k_hidden(const float* __restrict__ initW,const float* __restrict__ initB){
  int b=blockIdx.y;
  int n=blockIdx.x*8+(threadIdx.x>>5);
  int lane=threadIdx.x&31;
  const float* f=g_encfin+b*2*HH;
  const float* w=initW+n*2*HH;
  float acc=0;
  for (int k=lane;k<2*HH;k+=32) acc+=f[k]*w[k];
  acc=warp_sum(acc);
  if (lane==0){
    float hv=tanh_acc(acc+initB[n]);
    g_dech[0][b*HH+n]=hv;
    g_chvec[b*HH+n]=hv;
  }
}

// ---------------- decoder GRU step ----------------
#define SMEM_DEC ((BB*(HH+4)+BB*(DKX+4))*4)
__global__ void __launch_bounds__(128,1) k_dec_step(int t,int par,
                           const float* __restrict__ Wih,const float* __restrict__ Whh,
                           const float* __restrict__ bih,const float* __restrict__ bhh){
  extern __shared__ float smd[];
  float* hs=smd;
  float* xs=smd+BB*(HH+4);
  int tid=threadIdx.x;
  const float* hprev=g_dech[par];
  float* hnext=g_dech[par^1];
  for (int i=tid;i<BB*HH/4;i+=128){
    int bb=i>>7, k=(i&127)<<2;
    *(float4*)(hs+bb*(HH+4)+k)=((const float4*)hprev)[i];
  }
  for (int i=tid;i<BB*DKX;i+=128){
    int b=i/DKX, k=i%DKX; float v;
    if (k<EE) v=g_pe[(t*BB+b)*EE+k];
    else if (k<EE+HH) v=g_chvec[b*HH+(k-EE)];
    else v=g_up[b*2*AD+(k-EE-HH)];
    xs[b*(DKX+4)+k]=v;
  }
  __syncthreads();
  int b=tid&31, jl=tid>>5;
  int j=blockIdx.x*4+jl;
  const float* hb=hs+b*(HH+4);
  const float* xb=xs+b*(DKX+4);
  float xr=0,xz=0,xn=0;
  {
    const float* w0=Wih+(long)j*DKX;
    const float* w1=Wih+(long)(HH+j)*DKX;
    const float* w2=Wih+(long)(2*HH+j)*DKX;
    #pragma unroll 4
    for (int k=0;k<DKX;k+=4){
      float4 x4=*(const float4*)(xb+k);
      float4 w;
      w=*(const float4*)(w0+k); xr+=w.x*x4.x+w.y*x4.y+w.z*x4.z+w.w*x4.w;
      w=*(const float4*)(w1+k); xz+=w.x*x4.x+w.y*x4.y+w.z*x4.z+w.w*x4.w;
      w=*(const float4*)(w2+k); xn+=w.x*x4.x+w.y*x4.y+w.z*x4.z+w.w*x4.w;
    }
  }
  float hr=0,hz=0,hn=0;
  {
    const float* w0=Whh+(long)j*HH;
    const float* w1=Whh+(long)(HH+j)*HH;
    const float* w2=Whh+(long)(2*HH+j)*HH;
    #pragma unroll 4
    for (int k=0;k<HH;k+=4){
      float4 h4=*(const float4*)(hb+k);
      float4 w;
      w=*(const float4*)(w0+k); hr+=w.x*h4.x+w.y*h4.y+w.z*h4.z+w.w*h4.w;
      w=*(const float4*)(w1+k); hz+=w.x*h4.x+w.y*h4.y+w.z*h4.z+w.w*h4.w;
      w=*(const float4*)(w2+k); hn+=w.x*h4.x+w.y*h4.y+w.z*h4.z+w.w*h4.w;
    }
  }
  float ir=xr+bih[j], iz=xz+bih[HH+j], in_=xn+bih[2*HH+j];
  float gr=hr+bhh[j], gz=hz+bhh[HH+j], gn=hn+bhh[2*HH+j];
  float r=sigf(ir+gr), z=sigf(iz+gz);
  float n=tanh_acc(in_+r*gn);
  hnext[b*HH+j]=(1.f-z)*n+z*hb[j];
}

__global__ void k_qw(const float* __restrict__ queryW,int parn){
  int b=blockIdx.y;
  int n=blockIdx.x*8+(threadIdx.x>>5);
  int lane=threadIdx.x&31;
  const float* h=g_dech[parn]+b*HH;
  const float* w=queryW+n*HH;
  float acc=0;
  for (int k=lane;k<HH;k+=32) acc+=h[k]*w[k];
  acc=warp_sum(acc);
  if (lane==0) g_qW[b*HH+n]=acc;
}

__global__ void k_scores(const float* __restrict__ energyW,const int* __restrict__ mask){
  __shared__ float sq[HH];
  __shared__ float se[HH];
  int b=blockIdx.y, tid=threadIdx.x;
  for (int k=tid;k<HH;k+=256){ sq[k]=g_qW[b*HH+k]; se[k]=energyW[k]; }
  __syncthreads();
  int s=blockIdx.x*8+(tid>>5);
  int lane=tid&31;
  if (s<SS){
    const float* pk=g_PK+((long)b*SS+s)*HH;
    float acc=0;
    for (int k=lane;k<HH;k+=32) acc+=se[k]*tanh_acc(sq[k]+pk[k]);
    acc=warp_sum(acc);
    if (lane==0) g_scores[b*SS+s]=(mask[b*SS+s]==0)?-1e30f:acc;
  }
}

// fused: softmax over scores -> alphas; context = alphas @ EH; gp
__global__ void __launch_bounds__(1024) k_attn(const float* __restrict__ genpW,
                                               const float* __restrict__ genpb,
                                               int parn,int t){
  int b=blockIdx.x, tid=threadIdx.x;
  __shared__ float sal[SS];
  __shared__ float red[1024];
  const float* sc=g_scores+b*SS;
  float m=-1e30f;
  if (tid<SS) m=sc[tid];
  red[tid]=m; __syncthreads();
  for (int st=512;st;st>>=1){ if(tid<st) red[tid]=fmaxf(red[tid],red[tid+st]); __syncthreads(); }
  m=red[0]; __syncthreads();
  float e=(tid<SS)?__expf(sc[tid]-m):0.f;
  red[tid]=e; __syncthreads();
  for (int st=512;st;st>>=1){ if(tid<st) red[tid]+=red[tid+st]; __syncthreads(); }
  float inv=__fdividef(1.f,red[0]);
  __syncthreads();
  if (tid<SS){ float a=e*inv; sal[tid]=a; g_alphas[b*SS+tid]=a; }
  __syncthreads();
  const float* eh=g_EH+(long)b*SS*2*HH+tid;
  float acc=0;
  #pragma unroll 8
  for (int s=0;s<SS;s++) acc+=sal[s]*eh[(long)s*(2*HH)];
  g_context[b*2*HH+tid]=acc;
  float gpp=acc*genpW[tid];
  if (tid<HH) gpp+=g_dech[parn][b*HH+tid]*genpW[2*HH+tid];
  if (tid<EE) gpp+=g_pe[(t*BB+b)*EE+tid]*genpW[3*HH+tid];
  red[tid]=gpp; __syncthreads();
  for (int st=512;st;st>>=1){ if(tid<st) red[tid]+=red[tid+st]; __syncthreads(); }
  if (tid==0) g_gp[b]=sigf(red[0]+genpb[0]);
}

__global__ void k_ch(const float* __restrict__ chW,int parn){
  int b=blockIdx.y;
  int n=blockIdx.x*8+(threadIdx.x>>5);
  int lane=threadIdx.x&31;
  const float* q=g_dech[parn]+b*HH;
  const float* c=g_context+b*2*HH;
  const float* w=chW+(long)n*3*HH;
  float acc=0;
  for (int k=lane;k<HH;k+=32) acc+=q[k]*w[k];
  for (int k=lane;k<2*HH;k+=32) acc+=c[k]*w[HH+k];
  acc=warp_sum(acc);
  if (lane==0) g_chvec[b*HH+n]=tanh_acc(acc);
}

// ---------------- logits = chvec @ genW^T on TENSOR CORES (tf32 mma.sync) ----------------
#define GLS_SMEM ((32*520 + 128*68)*4)
__global__ void __launch_bounds__(256) k_genlogits_tf32(const float* __restrict__ A,
                                                        const float* __restrict__ W,
                                                        float* __restrict__ C){
  extern __shared__ float gls[];
  float* chS=gls;              // [32][520]
  float* BS =gls+32*520;       // [128][68]
  int tid=threadIdx.x, n0=blockIdx.x*128;
  int wid=tid>>5, lane=tid&31;
  for (int i=tid;i<32*128;i+=256){
    int m=i>>7, kq=i&127;
    float4 v=*((const float4*)(A+(long)m*HH)+kq);
    float* p=chS+m*520+kq*4;
    p[0]=to_tf32(v.x); p[1]=to_tf32(v.y); p[2]=to_tf32(v.z); p[3]=to_tf32(v.w);
  }
  float d[2][2][4];
  #pragma unroll
  for (int mt=0;mt<2;mt++)
    #pragma unroll
    for (int nt=0;nt<2;nt++)
      #pragma unroll
      for (int q=0;q<4;q++) d[mt][nt][q]=0.f;

  int r=lane>>2, c=lane&3;
  for (int k0=0;k0<HH;k0+=64){
    for (int i=tid;i<128*16;i+=256){
      int n=i>>4, kq=i&15;
      int gn=n0+n;
      float4 v;
      if (gn<VV) v=*((const float4*)(W+(long)gn*HH+k0)+kq);
      else { v.x=v.y=v.z=v.w=0.f; }
      float* p=BS+n*68+kq*4;
      p[0]=to_tf32(v.x); p[1]=to_tf32(v.y); p[2]=to_tf32(v.z); p[3]=to_tf32(v.w);
    }
    __syncthreads();
    #pragma unroll
    for (int kk=0;kk<64;kk+=8){
      unsigned a[2][4];
      #pragma unroll
      for (int mt=0;mt<2;mt++){
        const float* ap=chS+(mt*16+r)*520 + k0+kk+c;
        a[mt][0]=__float_as_uint(ap[0]);
        a[mt][1]=__float_as_uint(ap[8*520]);
        a[mt][2]=__float_as_uint(ap[4]);
        a[mt][3]=__float_as_uint(ap[8*520+4]);
      }
      unsigned bfr[2][2];
      #pragma unroll
      for (int nt=0;nt<2;nt++){
        const float* bp=BS+(wid*16+nt*8+r)*68 + kk+c;
        bfr[nt][0]=__float_as_uint(bp[0]);
        bfr[nt][1]=__float_as_uint(bp[4]);
      }
      #pragma unroll
      for (int mt=0;mt<2;mt++)
        #pragma unroll
        for (int nt=0;nt<2;nt++)
          asm volatile("mma.sync.aligned.m16n8k8.row.col.f32.tf32.tf32.f32 "
            "{%0,%1,%2,%3},{%4,%5,%6,%7},{%8,%9},{%0,%1,%2,%3};"
            :"+f"(d[mt][nt][0]),"+f"(d[mt][nt][1]),"+f"(d[mt][nt][2]),"+f"(d[mt][nt][3])
            :"r"(a[mt][0]),"r"(a[mt][1]),"r"(a[mt][2]),"r"(a[mt][3]),
             "r"(bfr[nt][0]),"r"(bfr[nt][1]));
    }
    __syncthreads();
  }
  #pragma unroll
  for (int mt=0;mt<2;mt++)
    #pragma unroll
    for (int nt=0;nt<2;nt++){
      int m=mt*16+r;
      int n=n0+wid*16+nt*8+2*c;
      if (n<VV){
        float2 v0; v0.x=d[mt][nt][0]; v0.y=d[mt][nt][1];
        float2 v1; v1.x=d[mt][nt][2]; v1.y=d[mt][nt][3];
        *(float2*)(C+(long)m*VV+n)=v0;
        *(float2*)(C+(long)(m+8)*VV+n)=v1;
      }
    }
}

__global__ void __launch_bounds__(1024) k_vocab_out(float* __restrict__ out,int t){
  int b=blockIdx.x, tid=threadIdx.x;
  __shared__ float red[1024];
  const float* lg=g_logits+(long)b*VV;
  float m=-1e30f;
  for (int v=tid*4;v<VV;v+=4096){
    float4 x=*(const float4*)(lg+v);
    m=fmaxf(m,fmaxf(fmaxf(x.x,x.y),fmaxf(x.z,x.w)));
  }
  red[tid]=m; __syncthreads();
  for (int st=512;st;st>>=1){ if(tid<st) red[tid]=fmaxf(red[tid],red[tid+st]); __syncthreads(); }
  m=red[0]; __syncthreads();
  float sum=0;
  for (int v=tid*4;v<VV;v+=4096){
    float4 x=*(const float4*)(lg+v);
    sum+=__expf(x.x-m)+__expf(x.y-m)+__expf(x.z-m)+__expf(x.w-m);
  }
  red[tid]=sum; __syncthreads();
  for (int st=512;st;st>>=1){ if(tid<st) red[tid]+=red[tid+st]; __syncthreads(); }
  float gp=g_gp[b];
  float inv=__fdividef(gp,red[0]);
  float* ob=out+(long)b*LL*VV+(long)t*VV;
  for (int v=tid*4;v<VV;v+=4096){
    float4 x=*(const float4*)(lg+v);
    float4 y;
    y.x=__expf(x.x-m)*inv; y.y=__expf(x.y-m)*inv;
    y.z=__expf(x.z-m)*inv; y.w=__expf(x.w-m)*inv;
    *(float4*)(ob+v)=y;
  }
}

__global__ void k_scatter(float* __restrict__ out,const int* __restrict__ src,int t){
  int i=blockIdx.x*256+threadIdx.x;
  if (i>=BB*SS) return;
  int b=i/SS, s=i%SS;
  float val=(1.f-g_gp[b])*g_alphas[i];
  atomicAdd(&out[(long)b*LL*VV+(long)t*VV+src[i]],val);
}

extern "C" void kernel_launch(void* const* d_in, const int* in_sizes, int n_in,
                              void* d_out, int out_size){
  int w=(in_sizes[5]==1)?6:5;
  const int* src =(const int*)d_in[0];
  const int* trg =(const int*)d_in[1];
  const int* user=(const int*)d_in[2];
  const int* prod=(const int*)d_in[3];
  const int* mask=(const int*)d_in[4];
  const float* embW  =(const float*)d_in[w+0];
  const float* userW =(const float*)d_in[w+1];
  const float* prodW =(const float*)d_in[w+2];
  const float* WihF  =(const float*)d_in[w+3];
  const float* WhhF  =(const float*)d_in[w+4];
  const float* bihF  =(const float*)d_in[w+5];
  const float* bhhF  =(const float*)d_in[w+6];
  const float* WihB  =(const float*)d_in[w+7];
  const float* WhhB  =(const float*)d_in[w+8];
  const float* bihB  =(const float*)d_in[w+9];
  const float* bhhB  =(const float*)d_in[w+10];
  const float* initW =(const float*)d_in[w+11];
  const float* initB =(const float*)d_in[w+12];
  const float* keyW  =(const float*)d_in[w+13];
  const float* queryW=(const float*)d_in[w+14];
  const float* energW=(const float*)d_in[w+15];
  const float* dWih  =(const float*)d_in[w+16];
  const float* dWhh  =(const float*)d_in[w+17];
  const float* dbih  =(const float*)d_in[w+18];
  const float* dbhh  =(const float*)d_in[w+19];
  const float* chW   =(const float*)d_in[w+20];
  const float* genpW =(const float*)d_in[w+21];
  const float* genpb =(const float*)d_in[w+22];
  const float* genW  =(const float*)d_in[w+23];
  float* out=(float*)d_out;

  float *pX,*pGiF,*pGiB,*pEH,*pPK,*pCh,*pLog;
  cudaGetSymbolAddress((void**)&pX,   g_x);
  cudaGetSymbolAddress((void**)&pGiF, g_gi_f);
  cudaGetSymbolAddress((void**)&pGiB, g_gi_b);
  cudaGetSymbolAddress((void**)&pEH,  g_EH);
  cudaGetSymbolAddress((void**)&pPK,  g_PK);
  cudaGetSymbolAddress((void**)&pCh,  g_chvec);
  cudaGetSymbolAddress((void**)&pLog, g_logits);

  cudaFuncSetAttribute(k_enc_persist,    cudaFuncAttributeMaxDynamicSharedMemorySize, SMEM_ENC);
  cudaFuncSetAttribute(k_dec_step,       cudaFuncAttributeMaxDynamicSharedMemorySize, SMEM_DEC);
  cudaFuncSetAttribute(k_genlogits_tf32, cudaFuncAttributeMaxDynamicSharedMemorySize, GLS_SMEM);

  k_embed<<<1024,256>>>(src,trg,user,prod,embW,userW,prodW);

  // gi (TRANSPOSED [s][n][b]) = x @ Wih^T + bih  — tf32 tensor cores
  {
    dim3 g(G3/128, (SS*BB)/64);
    gemm_tf32<true><<<g,256>>>(pX, WihF, bihF, pGiF, SS*BB, G3, EE);
    gemm_tf32<true><<<g,256>>>(pX, WihB, bihB, pGiB, SS*BB, G3, EE);
  }

  k_enc_persist<<<ENC_BLOCKS,256,SMEM_ENC>>>(WhhF,bhhF,WhhB,bhhB);

  k_postenc<<<2048,256>>>();

  // proj_key = EH @ keyW^T — tf32 tensor cores
  {
    dim3 g(HH/128, (SS*BB)/64);
    gemm_tf32<false><<<g,256>>>(pEH, keyW, nullptr, pPK, SS*BB, HH, 2*HH);
  }

  k_hidden<<<dim3(HH/8,BB),256>>>(initW, initB);

  for (int t=0;t<LL;t++){
    int par=t&1;
    k_dec_step<<<128,128,SMEM_DEC>>>(t,par,dWih,dWhh,dbih,dbhh);
    k_qw<<<dim3(HH/8,BB),256>>>(queryW, par^1);
    k_scores<<<dim3(SS/8,BB),256>>>(energW, mask);
    k_attn<<<BB,1024>>>(genpW, genpb, par^1, t);
    k_ch<<<dim3(HH/8,BB),256>>>(chW, par^1);
    k_genlogits_tf32<<<(VV+127)/128,256,GLS_SMEM>>>(pCh, genW, pLog);
    k_vocab_out<<<BB,1024>>>(out, t);
    k_scatter<<<(BB*SS+255)/256,256>>>(out, src, t);
  }
}